// round 4
// baseline (speedup 1.0000x reference)
#include <cuda_runtime.h>
#include <cuda_fp16.h>
#include <cstdint>

#define EE 256
#define HH 128
#define G4 512
#define BB 128
#define SS 1024
#define MM (SS*BB)
#define B512 (BB*G4)
#define NEGV -10000.0f

// scratch (static device memory)
__device__ float g_G[(size_t)2*SS*BB*G4];
__device__ float g_y1[(size_t)SS*BB*256];
__device__ float g_y2[(size_t)SS*BB*256];
__device__ float g_feats[(size_t)BB*SS*8];

__device__ __forceinline__ unsigned long long dup2(float a){
    unsigned long long r; asm("mov.b64 %0, {%1, %1};" : "=l"(r) : "f"(a)); return r;
}
__device__ __forceinline__ unsigned long long pk2(float a, float b){
    unsigned long long r; asm("mov.b64 %0, {%1, %2};" : "=l"(r) : "f"(a), "f"(b)); return r;
}
__device__ __forceinline__ void fma2(unsigned long long& d, unsigned long long a,
                                     unsigned long long b){
    asm("fma.rn.f32x2 %0, %1, %2, %0;" : "+l"(d) : "l"(a), "l"(b));
}
__device__ __forceinline__ float2 up2(unsigned long long v){
    float2 f; asm("mov.b64 {%0, %1}, %2;" : "=f"(f.x), "=f"(f.y) : "l"(v)); return f;
}
__device__ __forceinline__ float sigf(float x){
    return __fdividef(1.0f, 1.0f + __expf(-x));
}
__device__ __forceinline__ float tanhfast(float x){
    return __fdividef(2.0f, 1.0f + __expf(-2.0f * x)) - 1.0f;
}

// ---- K1/K3: G[d][t][b][512] = A[row] . W[n]^T + bih[n] + bhh[n] ----
__global__ __launch_bounds__(256) void gemm_proj(
    const float* __restrict__ Asrc, const int* __restrict__ tokens,
    const float* __restrict__ W, const float* __restrict__ bih,
    const float* __restrict__ bhh, float* __restrict__ G)
{
    __shared__ __align__(16) float As[16][64];
    __shared__ __align__(16) float Bs[16][64];
    __shared__ int rowidx[64];

    const int tid = threadIdx.x;
    const int n0 = blockIdx.x * 64;
    const int m0 = blockIdx.y * 64;

    if (tid < 64) rowidx[tid] = tokens ? tokens[m0 + tid] : (m0 + tid);
    __syncthreads();

    const int r = tid >> 2, c = tid & 3;
    const size_t arow = (size_t)rowidx[r] * 256;
    const float* wrow = W + (size_t)(n0 + r) * 256;
    const int ty = tid >> 4, tx = tid & 15;

    unsigned long long acc[4][2];
#pragma unroll
    for (int i = 0; i < 4; i++){ acc[i][0]=0ull; acc[i][1]=0ull; }

    for (int kc = 0; kc < 256; kc += 16){
        float4 av = *(const float4*)(Asrc + arow + kc + 4*c);
        float4 bv = *(const float4*)(wrow + kc + 4*c);
        As[4*c+0][r]=av.x; As[4*c+1][r]=av.y; As[4*c+2][r]=av.z; As[4*c+3][r]=av.w;
        Bs[4*c+0][r]=bv.x; Bs[4*c+1][r]=bv.y; Bs[4*c+2][r]=bv.z; Bs[4*c+3][r]=bv.w;
        __syncthreads();
#pragma unroll
        for (int kk = 0; kk < 16; kk++){
            float4 a = *(const float4*)&As[kk][ty*4];
            const unsigned long long* bp = (const unsigned long long*)&Bs[kk][tx*4];
            unsigned long long b0 = bp[0], b1 = bp[1];
            unsigned long long a0=dup2(a.x), a1=dup2(a.y), a2=dup2(a.z), a3=dup2(a.w);
            fma2(acc[0][0],a0,b0); fma2(acc[0][1],a0,b1);
            fma2(acc[1][0],a1,b0); fma2(acc[1][1],a1,b1);
            fma2(acc[2][0],a2,b0); fma2(acc[2][1],a2,b1);
            fma2(acc[3][0],a3,b0); fma2(acc[3][1],a3,b1);
        }
        __syncthreads();
    }

    const int d = n0 >> 9;
    const int j0 = (n0 & 511) + tx * 4;
    float bias[4];
#pragma unroll
    for (int q = 0; q < 4; q++){
        int n = n0 + tx*4 + q;
        bias[q] = bih[n] + bhh[n];
    }
#pragma unroll
    for (int i = 0; i < 4; i++){
        int m = m0 + ty*4 + i;
        float2 p0 = up2(acc[i][0]);
        float2 p1 = up2(acc[i][1]);
        float4 v = make_float4(p0.x+bias[0], p0.y+bias[1], p1.x+bias[2], p1.y+bias[3]);
        *(float4*)(G + ((size_t)d*MM + m)*G4 + j0) = v;
    }
}

// ---- K2/K4: recurrence. Block = (batch-pair, direction). Thread j owns gate row j. ----
__global__ __launch_bounds__(512, 1) void lstm_layer(
    const float* __restrict__ G, const float* __restrict__ whhL,
    const float* __restrict__ h0L, const float* __restrict__ c0L,
    float* __restrict__ Y)
{
    const int j = threadIdx.x;
    const int d = blockIdx.y;
    const int b0 = blockIdx.x * 2, b1 = b0 + 1;

    __shared__ __align__(16) float hcur[2][128];
    __shared__ float gbuf[2][512];

    const float* wr = whhL + ((size_t)d*G4 + j) * HH;
    half2 wh[64];
#pragma unroll
    for (int kk = 0; kk < 64; kk++)
        wh[kk] = __floats2half2_rn(wr[2*kk], wr[2*kk+1]);

    float cst0 = 0.f, cst1 = 0.f;
    if (j < 128){
        size_t base = (size_t)d * (BB*HH);
        hcur[0][j] = h0L[base + (size_t)b0*HH + j];
        hcur[1][j] = h0L[base + (size_t)b1*HH + j];
        cst0 = c0L[base + (size_t)b0*HH + j];
        cst1 = c0L[base + (size_t)b1*HH + j];
    }
    __syncthreads();

    const float* gp = G + (size_t)d*SS*BB*G4 + j;
    const size_t ob0 = (size_t)b0*G4, ob1 = ob0 + G4;

    int tfirst = d ? (SS-1) : 0;
    float gin0 = gp[(size_t)tfirst*B512 + ob0];
    float gin1 = gp[(size_t)tfirst*B512 + ob1];

    for (int s = 0; s < SS; s++){
        const int t = d ? (SS-1-s) : s;
        float ga = gin0, gb = gin1;
        if (s < SS-1){
            int tn = d ? (SS-2-s) : (s+1);
            size_t o = (size_t)tn*B512;
            gin0 = gp[o + ob0];
            gin1 = gp[o + ob1];
        }
        unsigned long long a0 = pk2(ga, 0.f);
        unsigned long long a1 = pk2(gb, 0.f);
#pragma unroll
        for (int kk = 0; kk < 64; kk++){
            float2 wf = __half22float2(wh[kk]);
            unsigned long long w2 = pk2(wf.x, wf.y);
            unsigned long long h0p = *(const unsigned long long*)&hcur[0][2*kk];
            unsigned long long h1p = *(const unsigned long long*)&hcur[1][2*kk];
            fma2(a0, w2, h0p);
            fma2(a1, w2, h1p);
        }
        float2 f0 = up2(a0), f1 = up2(a1);
        gbuf[0][j] = f0.x + f0.y;
        gbuf[1][j] = f1.x + f1.y;
        __syncthreads();

        if (j < 128){
            {
                float ig = sigf(gbuf[0][j]);
                float fg = sigf(gbuf[0][j+128]);
                float gg = tanhfast(gbuf[0][j+256]);
                float og = sigf(gbuf[0][j+384]);
                cst0 = fg*cst0 + ig*gg;
                float h = og * tanhfast(cst0);
                hcur[0][j] = h;
                Y[((size_t)t*BB + b0)*256 + d*128 + j] = h;
            }
            {
                float ig = sigf(gbuf[1][j]);
                float fg = sigf(gbuf[1][j+128]);
                float gg = tanhfast(gbuf[1][j+256]);
                float og = sigf(gbuf[1][j+384]);
                cst1 = fg*cst1 + ig*gg;
                float h = og * tanhfast(cst1);
                hcur[1][j] = h;
                Y[((size_t)t*BB + b1)*256 + d*128 + j] = h;
            }
        }
        __syncthreads();
    }
}

// ---- K5: feats[b][s][t] = y2[s*B+b,:] . w_out[t,:] + b_out[t], stride 8 ----
__global__ __launch_bounds__(256) void feats_kernel(
    const float* __restrict__ Y2, const float* __restrict__ wout,
    const float* __restrict__ bout, float* __restrict__ F)
{
    __shared__ float W[7][256];
    __shared__ float bo[7];
    const int tid = threadIdx.x;
    for (int i = tid; i < 7*256; i += 256) W[i>>8][i&255] = wout[i];
    if (tid < 7) bo[tid] = bout[tid];
    __syncthreads();

    const int warp = tid >> 5, lane = tid & 31;
    const size_t m = (size_t)blockIdx.x * 8 + warp;
    const float* yr = Y2 + m * 256;

    float acc[7] = {0,0,0,0,0,0,0};
#pragma unroll
    for (int i = 0; i < 8; i++){
        int k = lane + 32*i;
        float x = yr[k];
#pragma unroll
        for (int t = 0; t < 7; t++) acc[t] += x * W[t][k];
    }
#pragma unroll
    for (int t = 0; t < 7; t++)
        for (int off = 16; off; off >>= 1)
            acc[t] += __shfl_down_sync(0xffffffffu, acc[t], off);

    if (lane == 0){
        int s = (int)(m >> 7), b = (int)(m & 127);
        float* fo = F + ((size_t)b*SS + s)*8;
#pragma unroll
        for (int t = 0; t < 7; t++) fo[t] = acc[t] + bo[t];
    }
}

// ---- K6: Viterbi, one warp per batch element ----
__global__ __launch_bounds__(32) void viterbi_kernel(
    const float* __restrict__ F, const float* __restrict__ trans,
    float* __restrict__ out)
{
    __shared__ unsigned char bp[SS*8];
    const int b = blockIdx.x;
    const int lane = threadIdx.x;

    float tr[7];
#pragma unroll
    for (int p = 0; p < 7; p++) tr[p] = (lane < 7) ? trans[lane*7 + p] : 0.f;

    float fv = (lane == 5) ? 0.f : NEGV;   // START = 5
    const float* fb = F + (size_t)b*SS*8;

    for (int s = 0; s < SS; s++){
        float m = -3.4e38f;
        int arg = 0;
#pragma unroll
        for (int p = 0; p < 7; p++){
            float v = __shfl_sync(0xffffffffu, fv, p) + tr[p];
            if (v > m){ m = v; arg = p; }
        }
        if (lane < 7){
            fv = m + fb[s*8 + lane];
            bp[s*8 + lane] = (unsigned char)arg;
        }
    }
    __syncwarp();

    float term = fv + ((lane < 7) ? trans[6*7 + lane] : 0.f);  // STOP = 6
    if (lane >= 7) term = -3.4e38f;

    float bestv = -3.4e38f;
    int best = 0;
#pragma unroll
    for (int n = 0; n < 7; n++){
        float v = __shfl_sync(0xffffffffu, term, n);
        if (v > bestv){ bestv = v; best = n; }
    }

    if (lane == 0){
        out[(size_t)BB*SS + b] = bestv;
        float* po = out + (size_t)b*SS;
        int tag = best;
        for (int s = SS-1; s > 0; --s){
            po[s] = (float)tag;
            tag = bp[s*8 + tag];
        }
        po[0] = (float)tag;
    }
}

extern "C" void kernel_launch(void* const* d_in, const int* in_sizes, int n_in,
                              void* d_out, int out_size)
{
    const int*   sentence = (const int*)  d_in[0];
    const float* embed    = (const float*)d_in[1];
    const float* w_ih     = (const float*)d_in[2];
    const float* w_hh     = (const float*)d_in[3];
    const float* b_ih     = (const float*)d_in[4];
    const float* b_hh     = (const float*)d_in[5];
    const float* h0       = (const float*)d_in[6];
    const float* c0       = (const float*)d_in[7];
    const float* w_out    = (const float*)d_in[8];
    const float* b_out    = (const float*)d_in[9];
    const float* trans    = (const float*)d_in[10];
    float* out = (float*)d_out;

    float *G, *Y1, *Y2, *F;
    cudaGetSymbolAddress((void**)&G,  g_G);
    cudaGetSymbolAddress((void**)&Y1, g_y1);
    cudaGetSymbolAddress((void**)&Y2, g_y2);
    cudaGetSymbolAddress((void**)&F,  g_feats);

    dim3 ggrid(16, 2048);      // N-tiles x M-tiles (64x64)
    dim3 lgrid(64, 2);         // batch-pairs x directions

    // layer 1
    gemm_proj<<<ggrid, 256>>>(embed, sentence, w_ih, b_ih, b_hh, G);
    lstm_layer<<<lgrid, 512>>>(G, w_hh, h0, c0, Y1);
    // layer 2
    gemm_proj<<<ggrid, 256>>>(Y1, nullptr,
                              w_ih + (size_t)2*G4*EE,
                              b_ih + 2*G4, b_hh + 2*G4, G);
    lstm_layer<<<lgrid, 512>>>(G, w_hh + (size_t)2*G4*HH,
                               h0 + (size_t)2*BB*HH, c0 + (size_t)2*BB*HH, Y2);
    // feats + viterbi
    feats_kernel<<<MM/8, 256>>>(Y2, w_out, b_out, F);
    viterbi_kernel<<<BB, 32>>>(F, trans, out);
}